// round 4
// baseline (speedup 1.0000x reference)
#include <cuda_runtime.h>
#include <cuda_bf16.h>
#include <cstdint>

// Problem shape (fixed by reference)
#define PN 8
#define PH 32
#define PL 512
#define PS 512
#define PLS (PL * PS)
#define NROWS (PN * PL)   // 4096 (n,l) rows
#define MAXP 100
#define TPAD (MAXP + 1)   // 101: bank = (5h + p) % 32 across h
#define GRID 888          // 148 SMs * 6 blocks -> exactly one wave

__global__ __launch_bounds__(256, 6)
void gpe_kernel(const float* __restrict__ QK,
                const int* __restrict__ pos,
                const float* __restrict__ table,
                float* __restrict__ out) {
    __shared__ float t_sh[PH * TPAD];   // transposed table: t_sh[h*101 + p]

    const int tid = threadIdx.x;

    // Stage table ONCE per block (transposed), zeroing padding row 0.
    #pragma unroll 4
    for (int i = tid; i < PH * MAXP; i += 256) {
        const int p = i >> 5;
        const int h = i & 31;
        const float v = (p == 0) ? 0.0f : __ldg(&table[p * PH + h]);
        t_sh[h * TPAD + p] = v;
    }

    // Each thread owns one s4 (group of 4 s) and 16 of the 32 heads.
    const int s4 = tid & 127;
    const int h0 = tid >> 7;              // 0 or 1

    const int4* pos4 = reinterpret_cast<const int4*>(pos);

    int r = blockIdx.x;
    // Prefetch pos for the first row before the barrier
    int4 pp = __ldg(pos4 + (size_t)r * (PS / 4) + s4);

    __syncthreads();

    while (r < NROWS) {
        const int rn = r + GRID;
        int4 pnext;
        if (rn < NROWS)
            pnext = __ldg(pos4 + (size_t)rn * (PS / 4) + s4);

        const int n = r >> 9;              // / PL
        const int l = r & (PL - 1);
        const size_t base = ((size_t)n * PH + h0) * (size_t)PLS
                          + (size_t)l * PS + ((size_t)s4 << 2);

        #pragma unroll
        for (int kb = 0; kb < 4; kb++) {
            // 4 independent loads (h = h0 + 2*(4*kb + j)), batched for MLP
            const size_t idx0 = base + (size_t)(kb * 8) * PLS;
            float4 q0 = __ldcs(reinterpret_cast<const float4*>(QK + idx0));
            float4 q1 = __ldcs(reinterpret_cast<const float4*>(QK + idx0 + (size_t)2 * PLS));
            float4 q2 = __ldcs(reinterpret_cast<const float4*>(QK + idx0 + (size_t)4 * PLS));
            float4 q3 = __ldcs(reinterpret_cast<const float4*>(QK + idx0 + (size_t)6 * PLS));

            const int hbase = h0 + 8 * kb;
            const float* th0 = &t_sh[hbase * TPAD];
            const float* th1 = th0 + 2 * TPAD;
            const float* th2 = th0 + 4 * TPAD;
            const float* th3 = th0 + 6 * TPAD;

            q0.x += th0[pp.x]; q0.y += th0[pp.y]; q0.z += th0[pp.z]; q0.w += th0[pp.w];
            q1.x += th1[pp.x]; q1.y += th1[pp.y]; q1.z += th1[pp.z]; q1.w += th1[pp.w];
            q2.x += th2[pp.x]; q2.y += th2[pp.y]; q2.z += th2[pp.z]; q2.w += th2[pp.w];
            q3.x += th3[pp.x]; q3.y += th3[pp.y]; q3.z += th3[pp.z]; q3.w += th3[pp.w];

            __stcg(reinterpret_cast<float4*>(out + idx0), q0);
            __stcg(reinterpret_cast<float4*>(out + idx0 + (size_t)2 * PLS), q1);
            __stcg(reinterpret_cast<float4*>(out + idx0 + (size_t)4 * PLS), q2);
            __stcg(reinterpret_cast<float4*>(out + idx0 + (size_t)6 * PLS), q3);
        }

        pp = pnext;
        r = rn;
    }
}

extern "C" void kernel_launch(void* const* d_in, const int* in_sizes, int n_in,
                              void* d_out, int out_size) {
    const float* QK    = (const float*)d_in[0];
    const int*   pos   = (const int*)d_in[1];
    const float* table = (const float*)d_in[2];
    float* out = (float*)d_out;

    gpe_kernel<<<GRID, 256>>>(QK, pos, table, out);
}

// round 5
// speedup vs baseline: 1.1384x; 1.1384x over previous
#include <cuda_runtime.h>
#include <cuda_bf16.h>
#include <cstdint>

// Problem shape (fixed by reference)
#define PN 8
#define PH 32
#define PL 512
#define PS 512
#define PLS (PL * PS)
#define MAXP 100
#define TPAD (MAXP + 1)   // 101: bank = (5h + p) % 32 across h

__global__ __launch_bounds__(256, 6)
void gpe_kernel(const float* __restrict__ QK,
                const int* __restrict__ pos,
                const float* __restrict__ table,
                float* __restrict__ out) {
    __shared__ float t_sh[PH * TPAD];   // transposed table: t_sh[h*101 + p]

    const int bid = blockIdx.x;          // n*PL + l  (one (n,l) row per block)
    const int n = bid >> 9;
    const int l = bid & (PL - 1);
    const int tid = threadIdx.x;

    // Each thread owns one s4 (group of 4 s) and 16 of the 32 heads.
    const int s4 = tid & 127;
    const int h0 = tid >> 7;             // 0 or 1

    // Issue pos load FIRST so it overlaps the table staging below.
    const int4 pp = __ldg(reinterpret_cast<const int4*>(
        pos + ((size_t)n * PL + l) * PS) + s4);

    // Stage table (transposed), zeroing padding row 0.
    #pragma unroll 4
    for (int i = tid; i < PH * MAXP; i += 256) {
        const int p = i >> 5;
        const int h = i & 31;
        const float v = (p == 0) ? 0.0f : __ldg(&table[p * PH + h]);
        t_sh[h * TPAD + p] = v;
    }

    __syncthreads();

    const size_t base = ((size_t)n * PH + h0) * (size_t)PLS
                      + (size_t)l * PS + ((size_t)s4 << 2);

    #pragma unroll
    for (int kb = 0; kb < 4; kb++) {
        // 4 independent loads (h = h0 + 2*(4*kb + j)), batched for MLP
        const size_t idx0 = base + (size_t)(kb * 8) * PLS;
        float4 q0 = __ldcs(reinterpret_cast<const float4*>(QK + idx0));
        float4 q1 = __ldcs(reinterpret_cast<const float4*>(QK + idx0 + (size_t)2 * PLS));
        float4 q2 = __ldcs(reinterpret_cast<const float4*>(QK + idx0 + (size_t)4 * PLS));
        float4 q3 = __ldcs(reinterpret_cast<const float4*>(QK + idx0 + (size_t)6 * PLS));

        const int hbase = h0 + 8 * kb;
        const float* th0 = &t_sh[hbase * TPAD];
        const float* th1 = th0 + 2 * TPAD;
        const float* th2 = th0 + 4 * TPAD;
        const float* th3 = th0 + 6 * TPAD;

        q0.x += th0[pp.x]; q0.y += th0[pp.y]; q0.z += th0[pp.z]; q0.w += th0[pp.w];
        q1.x += th1[pp.x]; q1.y += th1[pp.y]; q1.z += th1[pp.z]; q1.w += th1[pp.w];
        q2.x += th2[pp.x]; q2.y += th2[pp.y]; q2.z += th2[pp.z]; q2.w += th2[pp.w];
        q3.x += th3[pp.x]; q3.y += th3[pp.y]; q3.z += th3[pp.z]; q3.w += th3[pp.w];

        __stcg(reinterpret_cast<float4*>(out + idx0), q0);
        __stcg(reinterpret_cast<float4*>(out + idx0 + (size_t)2 * PLS), q1);
        __stcg(reinterpret_cast<float4*>(out + idx0 + (size_t)4 * PLS), q2);
        __stcg(reinterpret_cast<float4*>(out + idx0 + (size_t)6 * PLS), q3);
    }
}

extern "C" void kernel_launch(void* const* d_in, const int* in_sizes, int n_in,
                              void* d_out, int out_size) {
    const float* QK    = (const float*)d_in[0];
    const int*   pos   = (const int*)d_in[1];
    const float* table = (const float*)d_in[2];
    float* out = (float*)d_out;

    const int blocks = PN * PL;   // 4096
    gpe_kernel<<<blocks, 256>>>(QK, pos, table, out);
}